// round 9
// baseline (speedup 1.0000x reference)
#include <cuda_runtime.h>

#define H 512
#define B 128
#define T 1024
#define NCLS 10

#define GRID 128
#define TPB 128
#define BT 32
#define JT 16
#define ROWP 68                   // padded h smem row stride (floats), 16B-aligned
#define WSM_FLOATS (4*256*32)     // 32768  (128 KB)
#define HSM_FLOATS (256*ROWP)     // 17408  (68 KB)
#define SMEM_BYTES ((WSM_FLOATS + HSM_FLOATS)*4)   // 200704

typedef unsigned long long ull;

// ---------------- device scratch (static, no allocation) ----------------
__device__ float g_xT[T * B];                // transposed x [t][b]
__device__ float g_hp[2][256 * B * 2];       // packed h: [k2][b][kbit]
__device__ unsigned g_cnt4[4];
__device__ unsigned g_gen4[4];

// ---------------- helpers ----------------
__device__ __forceinline__ ull fma2(ull a, ull b, ull c) {
    ull d;
    asm("fma.rn.f32x2 %0, %1, %2, %3;" : "=l"(d) : "l"(a), "l"(b), "l"(c));
    return d;
}
__device__ __forceinline__ float hadd2(ull a) {
    union { ull u; float2 f; } x; x.u = a;
    return x.f.x + x.f.y;
}
__device__ __forceinline__ float sigf(float x) {
    return __fdividef(1.0f, 1.0f + __expf(-x));
}
__device__ __forceinline__ float tanf_(float x) {
    return __fdividef(2.0f, 1.0f + __expf(-2.0f * x)) - 1.0f;
}

// group barrier: 32 blocks sharing bt; monotone generation targets
__device__ __forceinline__ void gbar(unsigned* cnt, unsigned* gen, unsigned target) {
    __syncthreads();
    if (threadIdx.x == 0) {
        unsigned old;
        asm volatile("atom.add.acq_rel.gpu.global.u32 %0, [%1], 1;"
                     : "=r"(old) : "l"(cnt) : "memory");
        if (old == 31u) {
            asm volatile("st.relaxed.gpu.global.u32 [%0], %1;"
                         :: "l"(cnt), "r"(0u) : "memory");
            asm volatile("st.release.gpu.global.u32 [%0], %1;"
                         :: "l"(gen), "r"(target) : "memory");
        } else {
            unsigned v;
            do {
                asm volatile("ld.acquire.gpu.global.u32 %0, [%1];"
                             : "=r"(v) : "l"(gen) : "memory");
            } while (v < target);
        }
    }
    __syncthreads();
}

// ---------------- single fused persistent kernel ----------------
__global__ void __launch_bounds__(TPB, 1)
lstm_fused(const float* __restrict__ x,
           const float* __restrict__ Wgx, const float* __restrict__ Wgh, const float* __restrict__ bg,
           const float* __restrict__ Wix, const float* __restrict__ Wih, const float* __restrict__ bi,
           const float* __restrict__ Wfx, const float* __restrict__ Wfh, const float* __restrict__ bf,
           const float* __restrict__ Wox, const float* __restrict__ Woh, const float* __restrict__ bo,
           const float* __restrict__ Wph, const float* __restrict__ bp,
           float* __restrict__ out) {
    extern __shared__ float smem[];
    float* Wsm = smem;                 // [g][k2][j*2 + kbit]   rows of 32 floats (128B)
    float* hsm = smem + WSM_FLOATS;    // [k2][bl*2 + kbit]     rows of 64 floats, stride ROWP

    const int tid  = threadIdx.x;
    const int warp = tid >> 5;
    const int lane = tid & 31;
    const int bt   = blockIdx.x >> 5;      // 0..3 (barrier group = b-slice)
    const int jt   = blockIdx.x & 31;      // 0..31
    const int b0b  = bt * BT;
    const int j0b  = jt * JT;
    const int bgrp = (warp << 2) | (lane >> 3);   // 0..15
    const int jgrp = lane & 7;                    // 0..7
    const int b0   = b0b + 2 * bgrp;              // this thread's 2 batches
    const int j0   = j0b + 2 * jgrp;              // this thread's 2 hidden cols

    unsigned* cnt = &g_cnt4[bt];
    unsigned* gen = &g_gen4[bt];

    // ---- phase 0a: transpose x slice (t in [jt*32, jt*32+32), b in this group's slice) ----
#pragma unroll
    for (int i = 0; i < 8; i++) {
        int idx = tid + i * TPB;               // 0..1023
        int tt  = jt * 32 + (idx >> 5);
        int bb  = b0b + (idx & 31);
        g_xT[tt * B + bb] = x[(size_t)bb * T + tt];
    }

    // ---- phase 0b: pack recurrent W tile into smem: Wsm[g][k2][jl*2 + (k&1)] ----
#pragma unroll
    for (int g = 0; g < 4; g++) {
        const float* S = (g == 0) ? Wgh : (g == 1) ? Wih : (g == 2) ? Wfh : Woh;
#pragma unroll
        for (int i = 0; i < 64; i++) {
            int idx = tid + i * TPB;           // 0..8191
            int k   = idx >> 4;                // 0..511
            int jl  = idx & 15;                // 0..15
            Wsm[(g * 256 + (k >> 1)) * 32 + jl * 2 + (k & 1)] = S[k * H + j0b + jl];
        }
    }

    // per-thread input-projection weights / biases for 2 j's x 4 gates
    float wxv[2][4], bv[2][4];
#pragma unroll
    for (int ji = 0; ji < 2; ji++) {
        int j = j0 + ji;
        wxv[ji][0] = Wgx[j]; wxv[ji][1] = Wix[j]; wxv[ji][2] = Wfx[j]; wxv[ji][3] = Wox[j];
        bv[ji][0]  = bg[j];  bv[ji][1]  = bi[j];  bv[ji][2]  = bf[j];  bv[ji][3]  = bo[j];
    }

    const float* hload = hsm + 4 * bgrp;              // + k2*ROWP
    const float* wload = Wsm + 4 * jgrp;              // + (g*256+k2)*32
    const int    hk2   = (j0 >> 1);                   // packed row this thread writes

    float c00 = 0.f, c01 = 0.f, c10 = 0.f, c11 = 0.f; // c[b][j]

    gbar(cnt, gen, 1u);   // xT visible group-wide; Wsm via the internal syncthreads

    for (int t = 0; t < T; t++) {
        float p[16];

        if (t > 0) {
            const float* hread = g_hp[t & 1];
            // --- stage packed h rows (ALL 256 rows x 64-float slice) into smem ---
            {
#pragma unroll
                for (int i = 0; i < 32; i++) {
                    int idx  = tid + i * TPB;          // 0..4095 float4
                    int row  = idx >> 4;               // 0..255
                    int c16  = idx & 15;
                    float4 v = __ldcg((const float4*)(hread + row * (B * 2) + b0b * 2) + c16);
                    *(float4*)(hsm + row * ROWP + c16 * 4) = v;
                }
            }
            __syncthreads();

            // --- GEMM: 2b x 2j x 4g, f32x2 over k-pairs, 1-phase LDS ---
            ull acc[16];       // [g*4 + bi*2 + ji]
#pragma unroll
            for (int i = 0; i < 16; i++) acc[i] = 0ull;

#pragma unroll 8
            for (int k2 = 0; k2 < 256; k2++) {
                ulonglong2 hv = *(const ulonglong2*)(hload + k2 * ROWP);
#pragma unroll
                for (int g = 0; g < 4; g++) {
                    ulonglong2 wv = *(const ulonglong2*)(wload + (g * 256 + k2) * 32);
                    acc[g * 4 + 0] = fma2(hv.x, wv.x, acc[g * 4 + 0]);  // b0,j0
                    acc[g * 4 + 1] = fma2(hv.x, wv.y, acc[g * 4 + 1]);  // b0,j1
                    acc[g * 4 + 2] = fma2(hv.y, wv.x, acc[g * 4 + 2]);  // b1,j0
                    acc[g * 4 + 3] = fma2(hv.y, wv.y, acc[g * 4 + 3]);  // b1,j1
                }
            }
#pragma unroll
            for (int i = 0; i < 16; i++) p[i] = hadd2(acc[i]);
        } else {
#pragma unroll
            for (int i = 0; i < 16; i++) p[i] = 0.f;
        }

        const float2 xv = *(const float2*)(g_xT + t * B + b0);

        // epilogue: 4 complete LSTM cells per thread (all gates local)
        float h00, h01, h10, h11;
        {
            float gv = tanf_(p[0]  + xv.x * wxv[0][0] + bv[0][0]);
            float iv = sigf (p[4]  + xv.x * wxv[0][1] + bv[0][1]);
            float fv = sigf (p[8]  + xv.x * wxv[0][2] + bv[0][2]);
            float ov = sigf (p[12] + xv.x * wxv[0][3] + bv[0][3]);
            c00 = gv * iv + c00 * fv;  h00 = tanf_(c00) * ov;
        }
        {
            float gv = tanf_(p[1]  + xv.x * wxv[1][0] + bv[1][0]);
            float iv = sigf (p[5]  + xv.x * wxv[1][1] + bv[1][1]);
            float fv = sigf (p[9]  + xv.x * wxv[1][2] + bv[1][2]);
            float ov = sigf (p[13] + xv.x * wxv[1][3] + bv[1][3]);
            c01 = gv * iv + c01 * fv;  h01 = tanf_(c01) * ov;
        }
        {
            float gv = tanf_(p[2]  + xv.y * wxv[0][0] + bv[0][0]);
            float iv = sigf (p[6]  + xv.y * wxv[0][1] + bv[0][1]);
            float fv = sigf (p[10] + xv.y * wxv[0][2] + bv[0][2]);
            float ov = sigf (p[14] + xv.y * wxv[0][3] + bv[0][3]);
            c10 = gv * iv + c10 * fv;  h10 = tanf_(c10) * ov;
        }
        {
            float gv = tanf_(p[3]  + xv.y * wxv[1][0] + bv[1][0]);
            float iv = sigf (p[7]  + xv.y * wxv[1][1] + bv[1][1]);
            float fv = sigf (p[11] + xv.y * wxv[1][2] + bv[1][2]);
            float ov = sigf (p[15] + xv.y * wxv[1][3] + bv[1][3]);
            c11 = gv * iv + c11 * fv;  h11 = tanf_(c11) * ov;
        }

        // packed h write: one STG.128 = (b0:j0,j1, b0+1:j0,j1) at row j0>>1
        {
            float* hwrite = g_hp[(t + 1) & 1];
            *(float4*)(hwrite + hk2 * (B * 2) + b0 * 2) = make_float4(h00, h01, h10, h11);
        }

        gbar(cnt, gen, (unsigned)(t + 2));
    }

    // ---- final projection for b_out (within this group's b-slice; h visible post-gbar) ----
    {
        const int b_out = b0b + jt;
        const float* hp0 = g_hp[0];               // T even -> final state in buffer 0
        float2 hv[8];
#pragma unroll
        for (int i = 0; i < 8; i++) {
            int k2 = lane + 32 * i;
            hv[i] = *(const float2*)(hp0 + k2 * (B * 2) + b_out * 2);
        }
        for (int ccl = warp; ccl < NCLS; ccl += 4) {
            const float* wr = Wph + ccl * H;
            float s = 0.f;
#pragma unroll
            for (int i = 0; i < 8; i++) {
                int k2 = lane + 32 * i;
                s += hv[i].x * wr[2 * k2] + hv[i].y * wr[2 * k2 + 1];
            }
#pragma unroll
            for (int off = 16; off; off >>= 1) s += __shfl_down_sync(0xffffffffu, s, off);
            if (lane == 0) out[b_out * NCLS + ccl] = s + bp[ccl];
        }
    }

    // ---- reset group counters for the next graph replay ----
    __syncthreads();
    if (tid == 0) {
        unsigned old = atomicAdd(cnt, 1u);
        if (old == 31u) {
            asm volatile("st.relaxed.gpu.global.u32 [%0], %1;"
                         :: "l"(cnt), "r"(0u) : "memory");
            asm volatile("st.relaxed.gpu.global.u32 [%0], %1;"
                         :: "l"(gen), "r"(0u) : "memory");
        }
    }
}

// ---------------- launch ----------------
extern "C" void kernel_launch(void* const* d_in, const int* in_sizes, int n_in,
                              void* d_out, int out_size) {
    const float* x   = (const float*)d_in[0];
    const float* Wgx = (const float*)d_in[1];
    const float* Wgh = (const float*)d_in[2];
    const float* bg  = (const float*)d_in[3];
    const float* Wix = (const float*)d_in[4];
    const float* Wih = (const float*)d_in[5];
    const float* bi  = (const float*)d_in[6];
    const float* Wfx = (const float*)d_in[7];
    const float* Wfh = (const float*)d_in[8];
    const float* bf  = (const float*)d_in[9];
    const float* Wox = (const float*)d_in[10];
    const float* Woh = (const float*)d_in[11];
    const float* bo  = (const float*)d_in[12];
    const float* Wph = (const float*)d_in[13];
    const float* bp  = (const float*)d_in[14];
    float* out = (float*)d_out;

    cudaFuncSetAttribute(lstm_fused, cudaFuncAttributeMaxDynamicSharedMemorySize,
                         SMEM_BYTES);

    lstm_fused<<<GRID, TPB, SMEM_BYTES>>>(x,
        Wgx, Wgh, bg, Wix, Wih, bi, Wfx, Wfh, bf, Wox, Woh, bo, Wph, bp, out);
}

// round 11
// speedup vs baseline: 1.9080x; 1.9080x over previous
#include <cuda_runtime.h>

typedef unsigned int   u32;
typedef unsigned short u16;

#define H 512
#define B 128
#define T 1024
#define NCLS 10
#define GRID 128
#define TPB 256

#define RSTRIDE 1040              // bytes per padded A/B smem row (520 halves)
#define SM_AHI 0                  // A hi : 32 rows
#define SM_ALO 33280              // A lo : 32 rows
#define SM_BHI 66560              // W hi : 64 rows
#define SM_BLO 133120             // W lo : 64 rows
#define SM_D   199680             // D: float[32][68]
#define SMEM_BYTES 208384

// ---------------- device scratch (static, no allocation) ----------------
__device__ uint4 g_hhi[2][B * H / 8];    // bf16 h hi, [b][k] rows
__device__ uint4 g_hlo[2][B * H / 8];    // bf16 h lo residual
__device__ unsigned g_cnt4[4];
__device__ unsigned g_gen4[4];

// ---------------- helpers ----------------
__device__ __forceinline__ u16 f2bf(float f) {
    u32 u = __float_as_uint(f);
    u32 r = (u + 0x7FFFu + ((u >> 16) & 1u)) >> 16;
    return (u16)r;
}
__device__ __forceinline__ float bf2f(u16 s) {
    return __uint_as_float(((u32)s) << 16);
}
__device__ __forceinline__ float sigf(float x) {
    return __fdividef(1.0f, 1.0f + __expf(-x));
}
__device__ __forceinline__ float tanf_(float x) {
    return __fdividef(2.0f, 1.0f + __expf(-2.0f * x)) - 1.0f;
}

__device__ __forceinline__ void mma16816(float* c, u32 a0, u32 a1, u32 a2, u32 a3,
                                         u32 b0, u32 b1) {
    asm volatile("mma.sync.aligned.m16n8k16.row.col.f32.bf16.bf16.f32 "
                 "{%0,%1,%2,%3}, {%4,%5,%6,%7}, {%8,%9}, {%0,%1,%2,%3};"
                 : "+f"(c[0]), "+f"(c[1]), "+f"(c[2]), "+f"(c[3])
                 : "r"(a0), "r"(a1), "r"(a2), "r"(a3), "r"(b0), "r"(b1));
}

// group barrier: 32 blocks sharing bt; monotone generation targets
__device__ __forceinline__ void gbar(unsigned* cnt, unsigned* gen, unsigned target) {
    __syncthreads();
    if (threadIdx.x == 0) {
        unsigned old;
        asm volatile("atom.add.acq_rel.gpu.global.u32 %0, [%1], 1;"
                     : "=r"(old) : "l"(cnt) : "memory");
        if (old == 31u) {
            asm volatile("st.relaxed.gpu.global.u32 [%0], %1;"
                         :: "l"(cnt), "r"(0u) : "memory");
            asm volatile("st.release.gpu.global.u32 [%0], %1;"
                         :: "l"(gen), "r"(target) : "memory");
        } else {
            unsigned v;
            do {
                asm volatile("ld.acquire.gpu.global.u32 %0, [%1];"
                             : "=r"(v) : "l"(gen) : "memory");
            } while (v < target);
        }
    }
    __syncthreads();
}

// ---------------- fused persistent tensor-core LSTM (mma.sync) ----------------
__global__ void __launch_bounds__(TPB, 1)
lstm_mma(const float* __restrict__ x,
         const float* __restrict__ Wgx, const float* __restrict__ Wgh, const float* __restrict__ bg,
         const float* __restrict__ Wix, const float* __restrict__ Wih, const float* __restrict__ bi,
         const float* __restrict__ Wfx, const float* __restrict__ Wfh, const float* __restrict__ bf,
         const float* __restrict__ Wox, const float* __restrict__ Woh, const float* __restrict__ bo,
         const float* __restrict__ Wph, const float* __restrict__ bp,
         float* __restrict__ out) {
    extern __shared__ char smem[];
    float* Dsm = (float*)(smem + SM_D);

    const int tid  = threadIdx.x;
    const int wid  = tid >> 5;
    const int lane = tid & 31;
    const int bt   = blockIdx.x >> 5;     // 0..3 (barrier group, batch slice)
    const int jt   = blockIdx.x & 31;     // 0..31
    const int b0b  = bt * 32;
    const int j0b  = jt * 16;

    unsigned* cnt = &g_cnt4[bt];
    unsigned* gen = &g_gen4[bt];

    // ---- pack W tile (bf16 hi/lo) into smem: row n = 4*jl + g, k contiguous ----
    for (int g = 0; g < 4; g++) {
        const float* S = (g == 0) ? Wgh : (g == 1) ? Wih : (g == 2) ? Wfh : Woh;
        for (int i = tid; i < 16 * 512; i += TPB) {
            int jl = i & 15;
            int k  = i >> 4;
            float w = S[k * H + j0b + jl];
            u16 hi = f2bf(w);
            u16 lo = f2bf(w - bf2f(hi));
            int n = jl * 4 + g;
            *(u16*)(smem + SM_BHI + n * RSTRIDE + k * 2) = hi;
            *(u16*)(smem + SM_BLO + n * RSTRIDE + k * 2) = lo;
        }
    }

    // ---- per-thread cells (fixed across time): idx = tid, tid+256 ----
    float wx[2][4], bv[2][4], cst[2];
    int cb[2], cj[2];
#pragma unroll
    for (int ci = 0; ci < 2; ci++) {
        int idx = tid + ci * 256;
        cb[ci] = idx >> 4;                 // 0..31 (batch within slice)
        cj[ci] = idx & 15;                 // 0..15 (j within tile)
        int j = j0b + cj[ci];
        wx[ci][0] = Wgx[j]; wx[ci][1] = Wix[j]; wx[ci][2] = Wfx[j]; wx[ci][3] = Wox[j];
        bv[ci][0] = bg[j];  bv[ci][1] = bi[j];  bv[ci][2] = bf[j];  bv[ci][3] = bo[j];
        cst[ci] = 0.f;
    }

    // ---- warp GEMM coordinates ----
    const int wm = wid >> 2;              // 0..1 -> m0 = wm*16
    const int wn = wid & 3;               // 0..3 -> n0 = wn*16
    const int m0 = wm * 16;
    const int n0 = wn * 16;
    const int aoff = (m0 + (lane >> 2)) * RSTRIDE + (lane & 3) * 4;
    const int boff = (n0 + (lane >> 2)) * RSTRIDE + (lane & 3) * 4;

    __syncthreads();   // W pack done

    for (int t = 0; t < T; t++) {
        if (t > 0) {
            // ---- stage h hi/lo (32 rows x 512 bf16 each) into padded smem rows ----
            const uint4* shi = g_hhi[t & 1];
            const uint4* slo = g_hlo[t & 1];
#pragma unroll
            for (int i = 0; i < 8; i++) {
                int idx = tid + i * TPB;           // 0..2047
                int r   = idx >> 6;                // 0..31
                int c   = idx & 63;                // uint4 within row
                uint4 vh = __ldcg(shi + ((b0b + r) * H >> 3) + c);
                uint4 vl = __ldcg(slo + ((b0b + r) * H >> 3) + c);
                *(uint4*)(smem + SM_AHI + r * RSTRIDE + c * 16) = vh;
                *(uint4*)(smem + SM_ALO + r * RSTRIDE + c * 16) = vl;
            }
            __syncthreads();

            // ---- 3-pass GEMM: hi*Whi + lo*Whi + hi*Wlo ----
            float acc0[4] = {0.f, 0.f, 0.f, 0.f};
            float acc1[4] = {0.f, 0.f, 0.f, 0.f};
#pragma unroll 1
            for (int pass = 0; pass < 3; pass++) {
                const char* Ab = smem + (pass == 1 ? SM_ALO : SM_AHI) + aoff;
                const char* Bb = smem + (pass == 2 ? SM_BLO : SM_BHI) + boff;
#pragma unroll 8
                for (int kc = 0; kc < 32; kc++) {
                    const int kb = kc * 32;
                    u32 a0 = *(const u32*)(Ab + kb);
                    u32 a1 = *(const u32*)(Ab + 8 * RSTRIDE + kb);
                    u32 a2 = *(const u32*)(Ab + kb + 16);
                    u32 a3 = *(const u32*)(Ab + 8 * RSTRIDE + kb + 16);
                    u32 b0 = *(const u32*)(Bb + kb);
                    u32 b1 = *(const u32*)(Bb + kb + 16);
                    mma16816(acc0, a0, a1, a2, a3, b0, b1);
                    u32 b2 = *(const u32*)(Bb + 8 * RSTRIDE + kb);
                    u32 b3 = *(const u32*)(Bb + 8 * RSTRIDE + kb + 16);
                    mma16816(acc1, a0, a1, a2, a3, b2, b3);
                }
            }

            // ---- D -> smem (m16n8 fragment layout) ----
            {
                const int dr = m0 + (lane >> 2);
                const int dc = n0 + 2 * (lane & 3);
                *(float2*)(Dsm + dr * 68 + dc)           = make_float2(acc0[0], acc0[1]);
                *(float2*)(Dsm + (dr + 8) * 68 + dc)     = make_float2(acc0[2], acc0[3]);
                *(float2*)(Dsm + dr * 68 + dc + 8)       = make_float2(acc1[0], acc1[1]);
                *(float2*)(Dsm + (dr + 8) * 68 + dc + 8) = make_float2(acc1[2], acc1[3]);
            }
            __syncthreads();
        }

        // ---- epilogue: 2 cells/thread ----
        u16* whi = (u16*)g_hhi[(t + 1) & 1];
        u16* wlo = (u16*)g_hlo[(t + 1) & 1];
#pragma unroll
        for (int ci = 0; ci < 2; ci++) {
            float4 dv;
            if (t > 0) dv = *(const float4*)(Dsm + cb[ci] * 68 + cj[ci] * 4);
            else       dv = make_float4(0.f, 0.f, 0.f, 0.f);
            const float xv = __ldg(x + (size_t)(b0b + cb[ci]) * T + t);
            float gv = tanf_(dv.x + xv * wx[ci][0] + bv[ci][0]);
            float iv = sigf (dv.y + xv * wx[ci][1] + bv[ci][1]);
            float fv = sigf (dv.z + xv * wx[ci][2] + bv[ci][2]);
            float ov = sigf (dv.w + xv * wx[ci][3] + bv[ci][3]);
            cst[ci] = gv * iv + cst[ci] * fv;
            float hv = tanf_(cst[ci]) * ov;
            u16 hi = f2bf(hv);
            u16 lo = f2bf(hv - bf2f(hi));
            const int gidx = (b0b + cb[ci]) * H + j0b + cj[ci];
            whi[gidx] = hi;
            wlo[gidx] = lo;
        }

        gbar(cnt, gen, (unsigned)(t + 1));
    }

    // ---- final projection: block handles batch b_out = b0b + jt ----
    {
        const u16* fhi = (const u16*)g_hhi[0];     // T even -> final state in buffer 0
        const u16* flo = (const u16*)g_hlo[0];
        const int b_out = b0b + jt;
        for (int cls = wid; cls < NCLS; cls += 8) {
            const float* wr = Wph + cls * H;
            float s = 0.f;
#pragma unroll
            for (int k = lane; k < H; k += 32) {
                float hv = bf2f(fhi[b_out * H + k]) + bf2f(flo[b_out * H + k]);
                s += hv * wr[k];
            }
#pragma unroll
            for (int off = 16; off; off >>= 1) s += __shfl_down_sync(0xffffffffu, s, off);
            if (lane == 0) out[b_out * NCLS + cls] = s + bp[cls];
        }
    }

    // ---- reset group counters for the next graph replay ----
    __syncthreads();
    if (tid == 0) {
        unsigned old = atomicAdd(cnt, 1u);
        if (old == 31u) {
            asm volatile("st.relaxed.gpu.global.u32 [%0], %1;"
                         :: "l"(cnt), "r"(0u) : "memory");
            asm volatile("st.relaxed.gpu.global.u32 [%0], %1;"
                         :: "l"(gen), "r"(0u) : "memory");
        }
    }
}

// ---------------- launch ----------------
extern "C" void kernel_launch(void* const* d_in, const int* in_sizes, int n_in,
                              void* d_out, int out_size) {
    const float* x   = (const float*)d_in[0];
    const float* Wgx = (const float*)d_in[1];
    const float* Wgh = (const float*)d_in[2];
    const float* bg  = (const float*)d_in[3];
    const float* Wix = (const float*)d_in[4];
    const float* Wih = (const float*)d_in[5];
    const float* bi  = (const float*)d_in[6];
    const float* Wfx = (const float*)d_in[7];
    const float* Wfh = (const float*)d_in[8];
    const float* bf  = (const float*)d_in[9];
    const float* Wox = (const float*)d_in[10];
    const float* Woh = (const float*)d_in[11];
    const float* bo  = (const float*)d_in[12];
    const float* Wph = (const float*)d_in[13];
    const float* bp  = (const float*)d_in[14];
    float* out = (float*)d_out;

    cudaFuncSetAttribute(lstm_mma, cudaFuncAttributeMaxDynamicSharedMemorySize, SMEM_BYTES);

    lstm_mma<<<GRID, TPB, SMEM_BYTES>>>(x,
        Wgx, Wgh, bg, Wix, Wih, bi, Wfx, Wfh, bf, Wox, Woh, bo, Wph, bp, out);
}

// round 13
// speedup vs baseline: 2.4005x; 1.2581x over previous
#include <cuda_runtime.h>

typedef unsigned int   u32;
typedef unsigned short u16;

#define H 512
#define B 128
#define T 1024
#define NCLS 10
#define GRID 128
#define TPB 256

#define RSTRIDE 1040              // bytes per padded A/B smem row (520 halves)
#define SM_AHI 0                  // A hi : 32 rows
#define SM_ALO 33280              // A lo : 32 rows
#define SM_BHI 66560              // W hi : 64 rows
#define SM_BLO 133120             // W lo : 64 rows
#define SM_D   199680             // D: float[2][32][68] (k-slice partials)
#define SMEM_BYTES (199680 + 2*32*68*4)   // 217088

// ---------------- device scratch (static, no allocation) ----------------
__device__ uint4 g_hhi[2][B * H / 8];    // bf16 h hi, [b][k] rows
__device__ uint4 g_hlo[2][B * H / 8];    // bf16 h lo residual
__device__ unsigned g_cnt4[4];
__device__ unsigned g_gen4[4];

// ---------------- helpers ----------------
__device__ __forceinline__ u16 f2bf(float f) {
    u32 u = __float_as_uint(f);
    u32 r = (u + 0x7FFFu + ((u >> 16) & 1u)) >> 16;
    return (u16)r;
}
__device__ __forceinline__ float bf2f(u16 s) {
    return __uint_as_float(((u32)s) << 16);
}
__device__ __forceinline__ float sigf(float x) {
    return __fdividef(1.0f, 1.0f + __expf(-x));
}
__device__ __forceinline__ float tanf_(float x) {
    return __fdividef(2.0f, 1.0f + __expf(-2.0f * x)) - 1.0f;
}

__device__ __forceinline__ void mma16816(float* c, u32 a0, u32 a1, u32 a2, u32 a3,
                                         u32 b0, u32 b1) {
    asm volatile("mma.sync.aligned.m16n8k16.row.col.f32.bf16.bf16.f32 "
                 "{%0,%1,%2,%3}, {%4,%5,%6,%7}, {%8,%9}, {%0,%1,%2,%3};"
                 : "+f"(c[0]), "+f"(c[1]), "+f"(c[2]), "+f"(c[3])
                 : "r"(a0), "r"(a1), "r"(a2), "r"(a3), "r"(b0), "r"(b1));
}

// group barrier: 32 blocks sharing bt; monotone generation targets
__device__ __forceinline__ void gbar(unsigned* cnt, unsigned* gen, unsigned target) {
    __syncthreads();
    if (threadIdx.x == 0) {
        unsigned old;
        asm volatile("atom.add.acq_rel.gpu.global.u32 %0, [%1], 1;"
                     : "=r"(old) : "l"(cnt) : "memory");
        if (old == 31u) {
            asm volatile("st.relaxed.gpu.global.u32 [%0], %1;"
                         :: "l"(cnt), "r"(0u) : "memory");
            asm volatile("st.release.gpu.global.u32 [%0], %1;"
                         :: "l"(gen), "r"(target) : "memory");
        } else {
            unsigned v;
            do {
                asm volatile("ld.acquire.gpu.global.u32 %0, [%1];"
                             : "=r"(v) : "l"(gen) : "memory");
            } while (v < target);
        }
    }
    __syncthreads();
}

// ---------------- fused persistent tensor-core LSTM (mma.sync) ----------------
__global__ void __launch_bounds__(TPB, 1)
lstm_mma(const float* __restrict__ x,
         const float* __restrict__ Wgx, const float* __restrict__ Wgh, const float* __restrict__ bg,
         const float* __restrict__ Wix, const float* __restrict__ Wih, const float* __restrict__ bi,
         const float* __restrict__ Wfx, const float* __restrict__ Wfh, const float* __restrict__ bf,
         const float* __restrict__ Wox, const float* __restrict__ Woh, const float* __restrict__ bo,
         const float* __restrict__ Wph, const float* __restrict__ bp,
         float* __restrict__ out) {
    extern __shared__ char smem[];
    float* Dsm = (float*)(smem + SM_D);

    const int tid  = threadIdx.x;
    const int wid  = tid >> 5;
    const int lane = tid & 31;
    const int bt   = blockIdx.x >> 5;     // 0..3 (barrier group, batch slice)
    const int jt   = blockIdx.x & 31;     // 0..31
    const int b0b  = bt * 32;
    const int j0b  = jt * 16;

    unsigned* cnt = &g_cnt4[bt];
    unsigned* gen = &g_gen4[bt];

    // ---- pack W tile (bf16 hi/lo) into smem: row n = 4*jl + g, k contiguous ----
    for (int g = 0; g < 4; g++) {
        const float* S = (g == 0) ? Wgh : (g == 1) ? Wih : (g == 2) ? Wfh : Woh;
        for (int i = tid; i < 16 * 512; i += TPB) {
            int jl = i & 15;
            int k  = i >> 4;
            float w = S[k * H + j0b + jl];
            u16 hi = f2bf(w);
            u16 lo = f2bf(w - bf2f(hi));
            int n = jl * 4 + g;
            *(u16*)(smem + SM_BHI + n * RSTRIDE + k * 2) = hi;
            *(u16*)(smem + SM_BLO + n * RSTRIDE + k * 2) = lo;
        }
    }

    // ---- per-thread cells (fixed across time): idx = tid, tid+256 ----
    float wx[2][4], bv[2][4], cst[2];
    int cb[2], cj[2];
#pragma unroll
    for (int ci = 0; ci < 2; ci++) {
        int idx = tid + ci * 256;
        cb[ci] = idx >> 4;                 // 0..31 (batch within slice)
        cj[ci] = idx & 15;                 // 0..15 (j within tile)
        int j = j0b + cj[ci];
        wx[ci][0] = Wgx[j]; wx[ci][1] = Wix[j]; wx[ci][2] = Wfx[j]; wx[ci][3] = Wox[j];
        bv[ci][0] = bg[j];  bv[ci][1] = bi[j];  bv[ci][2] = bf[j];  bv[ci][3] = bo[j];
        cst[ci] = 0.f;
    }

    // ---- warp GEMM coordinates: m32 x n16 tile, k-slice of 256 ----
    const int wn = wid & 3;               // n-tile -> n0 = wn*16
    const int ks = wid >> 2;              // k-slice 0/1 -> k base = ks*256
    const int n0 = wn * 16;
    const int kbase = ks * 512;           // byte offset of k-slice start (256 halves)
    const int aoff = (lane >> 2) * RSTRIDE + (lane & 3) * 4 + kbase;
    const int boff = (n0 + (lane >> 2)) * RSTRIDE + (lane & 3) * 4 + kbase;

    __syncthreads();   // W pack done

    for (int t = 0; t < T; t++) {
        if (t > 0) {
            // ---- stage h hi/lo (32 rows x 512 bf16 each) into padded smem rows ----
            const uint4* shi = g_hhi[t & 1];
            const uint4* slo = g_hlo[t & 1];
#pragma unroll
            for (int i = 0; i < 8; i++) {
                int idx = tid + i * TPB;           // 0..2047
                int r   = idx >> 6;                // 0..31
                int c   = idx & 63;                // uint4 within row
                uint4 vh = __ldcg(shi + ((b0b + r) * H >> 3) + c);
                uint4 vl = __ldcg(slo + ((b0b + r) * H >> 3) + c);
                *(uint4*)(smem + SM_AHI + r * RSTRIDE + c * 16) = vh;
                *(uint4*)(smem + SM_ALO + r * RSTRIDE + c * 16) = vl;
            }
            __syncthreads();

            // ---- fused 3-product GEMM over my k-slice: m32 x n16 ----
            float acc[4][4];               // [mtile*2 + nblk][4]
#pragma unroll
            for (int i = 0; i < 4; i++)
#pragma unroll
                for (int q = 0; q < 4; q++) acc[i][q] = 0.f;

            const char* Ah = smem + SM_AHI + aoff;
            const char* Al = smem + SM_ALO + aoff;
            const char* Bh = smem + SM_BHI + boff;
            const char* Bl = smem + SM_BLO + boff;

#pragma unroll 4
            for (int kc = 0; kc < 16; kc++) {
                const int kb = kc * 32;
                // A fragments: 2 m-tiles (rows +0 / +16), hi & lo
                u32 ah[2][4], al[2][4];
#pragma unroll
                for (int mtile = 0; mtile < 2; mtile++) {
                    const int mo = mtile * 16 * RSTRIDE;
                    ah[mtile][0] = *(const u32*)(Ah + mo + kb);
                    ah[mtile][1] = *(const u32*)(Ah + mo + 8 * RSTRIDE + kb);
                    ah[mtile][2] = *(const u32*)(Ah + mo + kb + 16);
                    ah[mtile][3] = *(const u32*)(Ah + mo + 8 * RSTRIDE + kb + 16);
                    al[mtile][0] = *(const u32*)(Al + mo + kb);
                    al[mtile][1] = *(const u32*)(Al + mo + 8 * RSTRIDE + kb);
                    al[mtile][2] = *(const u32*)(Al + mo + kb + 16);
                    al[mtile][3] = *(const u32*)(Al + mo + 8 * RSTRIDE + kb + 16);
                }
                // B fragments: 2 n-blocks (n +0 / +8), hi & lo
                u32 bh[2][2], bl[2][2];
                bh[0][0] = *(const u32*)(Bh + kb);
                bh[0][1] = *(const u32*)(Bh + kb + 16);
                bh[1][0] = *(const u32*)(Bh + 8 * RSTRIDE + kb);
                bh[1][1] = *(const u32*)(Bh + 8 * RSTRIDE + kb + 16);
                bl[0][0] = *(const u32*)(Bl + kb);
                bl[0][1] = *(const u32*)(Bl + kb + 16);
                bl[1][0] = *(const u32*)(Bl + 8 * RSTRIDE + kb);
                bl[1][1] = *(const u32*)(Bl + 8 * RSTRIDE + kb + 16);

#pragma unroll
                for (int mtile = 0; mtile < 2; mtile++) {
#pragma unroll
                    for (int nb = 0; nb < 2; nb++) {
                        float* a = acc[mtile * 2 + nb];
                        mma16816(a, ah[mtile][0], ah[mtile][1], ah[mtile][2], ah[mtile][3],
                                 bh[nb][0], bh[nb][1]);                     // hi * Whi
                        mma16816(a, al[mtile][0], al[mtile][1], al[mtile][2], al[mtile][3],
                                 bh[nb][0], bh[nb][1]);                     // lo * Whi
                        mma16816(a, ah[mtile][0], ah[mtile][1], ah[mtile][2], ah[mtile][3],
                                 bl[nb][0], bl[nb][1]);                     // hi * Wlo
                    }
                }
            }

            // ---- D partial -> smem slice ks (m16n8 fragment layout) ----
            {
                float* Dk = Dsm + ks * (32 * 68);
                const int r  = lane >> 2;
                const int dc = n0 + 2 * (lane & 3);
#pragma unroll
                for (int mtile = 0; mtile < 2; mtile++) {
                    const int dr = mtile * 16 + r;
                    float* a0 = acc[mtile * 2 + 0];
                    float* a1 = acc[mtile * 2 + 1];
                    *(float2*)(Dk + dr * 68 + dc)           = make_float2(a0[0], a0[1]);
                    *(float2*)(Dk + (dr + 8) * 68 + dc)     = make_float2(a0[2], a0[3]);
                    *(float2*)(Dk + dr * 68 + dc + 8)       = make_float2(a1[0], a1[1]);
                    *(float2*)(Dk + (dr + 8) * 68 + dc + 8) = make_float2(a1[2], a1[3]);
                }
            }
            __syncthreads();
        }

        // ---- epilogue: 2 cells/thread (sum the 2 k-slice partials) ----
        u16* whi = (u16*)g_hhi[(t + 1) & 1];
        u16* wlo = (u16*)g_hlo[(t + 1) & 1];
#pragma unroll
        for (int ci = 0; ci < 2; ci++) {
            float4 dv;
            if (t > 0) {
                float4 d0 = *(const float4*)(Dsm + cb[ci] * 68 + cj[ci] * 4);
                float4 d1 = *(const float4*)(Dsm + 32 * 68 + cb[ci] * 68 + cj[ci] * 4);
                dv = make_float4(d0.x + d1.x, d0.y + d1.y, d0.z + d1.z, d0.w + d1.w);
            } else {
                dv = make_float4(0.f, 0.f, 0.f, 0.f);
            }
            const float xv = __ldg(x + (size_t)(b0b + cb[ci]) * T + t);
            float gv = tanf_(dv.x + xv * wx[ci][0] + bv[ci][0]);
            float iv = sigf (dv.y + xv * wx[ci][1] + bv[ci][1]);
            float fv = sigf (dv.z + xv * wx[ci][2] + bv[ci][2]);
            float ov = sigf (dv.w + xv * wx[ci][3] + bv[ci][3]);
            cst[ci] = gv * iv + cst[ci] * fv;
            float hv = tanf_(cst[ci]) * ov;
            u16 hi = f2bf(hv);
            u16 lo = f2bf(hv - bf2f(hi));
            const int gidx = (b0b + cb[ci]) * H + j0b + cj[ci];
            whi[gidx] = hi;
            wlo[gidx] = lo;
        }

        gbar(cnt, gen, (unsigned)(t + 1));
    }

    // ---- final projection: block handles batch b_out = b0b + jt ----
    {
        const u16* fhi = (const u16*)g_hhi[0];     // T even -> final state in buffer 0
        const u16* flo = (const u16*)g_hlo[0];
        const int b_out = b0b + jt;
        for (int cls = wid; cls < NCLS; cls += 8) {
            const float* wr = Wph + cls * H;
            float s = 0.f;
#pragma unroll
            for (int k = lane; k < H; k += 32) {
                float hv = bf2f(fhi[b_out * H + k]) + bf2f(flo[b_out * H + k]);
                s += hv * wr[k];
            }
#pragma unroll
            for (int off = 16; off; off >>= 1) s += __shfl_down_sync(0xffffffffu, s, off);
            if (lane == 0) out[b_out * NCLS + cls] = s + bp[cls];
        }
    }

    // ---- reset group counters for the next graph replay ----
    __syncthreads();
    if (tid == 0) {
        unsigned old = atomicAdd(cnt, 1u);
        if (old == 31u) {
            asm volatile("st.relaxed.gpu.global.u32 [%0], %1;"
                         :: "l"(cnt), "r"(0u) : "memory");
            asm volatile("st.relaxed.gpu.global.u32 [%0], %1;"
                         :: "l"(gen), "r"(0u) : "memory");
        }
    }
}

// ---------------- launch ----------------
extern "C" void kernel_launch(void* const* d_in, const int* in_sizes, int n_in,
                              void* d_out, int out_size) {
    const float* x   = (const float*)d_in[0];
    const float* Wgx = (const float*)d_in[1];
    const float* Wgh = (const float*)d_in[2];
    const float* bg  = (const float*)d_in[3];
    const float* Wix = (const float*)d_in[4];
    const float* Wih = (const float*)d_in[5];
    const float* bi  = (const float*)d_in[6];
    const float* Wfx = (const float*)d_in[7];
    const float* Wfh = (const float*)d_in[8];
    const float* bf  = (const float*)d_in[9];
    const float* Wox = (const float*)d_in[10];
    const float* Woh = (const float*)d_in[11];
    const float* bo  = (const float*)d_in[12];
    const float* Wph = (const float*)d_in[13];
    const float* bp  = (const float*)d_in[14];
    float* out = (float*)d_out;

    cudaFuncSetAttribute(lstm_mma, cudaFuncAttributeMaxDynamicSharedMemorySize, SMEM_BYTES);

    lstm_mma<<<GRID, TPB, SMEM_BYTES>>>(x,
        Wgx, Wgh, bg, Wix, Wih, bi, Wfx, Wfh, bf, Wox, Woh, bo, Wph, bp, out);
}